// round 6
// baseline (speedup 1.0000x reference)
#include <cuda_runtime.h>
#include <cstddef>

// VQ nearest-neighbor quantization
// x: [32,64,64,64] f32 (B,C,H,W), codebook: [512,64] f32
// out: codes [B,C,H,W] f32 (8388608) followed by indices [B,H,W] as f32 (131072)

#define KCODES 512
#define DCH    64
#define BATCH  32
#define HH     64
#define WW     64
#define NTILES (BATCH*HH)       // 2048
#define CSTR   65               // codebook row stride (64 data + 1 halfnorm)
#define THREADS 256
#define RED_STR 17
#define MARGIN 1e-2f            // near-tie refinement margin (score units)

#define CODES_ELEMS ((size_t)BATCH*DCH*HH*WW)   // 8388608
#define IDX_ELEMS   ((size_t)BATCH*HH*WW)       // 131072

// shared layout (floats)
#define CS_FLOATS  (KCODES*CSTR)   // 33280
#define XS_FLOATS  (DCH*WW)        // 4096
#define RED_FLOATS (WW*RED_STR)    // 1088
// cs + xs + rv + r2v + ri + r2i + idx
#define SMEM_BYTES ((CS_FLOATS + XS_FLOATS + 4*RED_FLOATS + WW)*4)

__device__ __forceinline__ unsigned long long ffma2(unsigned long long a,
                                                    unsigned long long b,
                                                    unsigned long long c) {
    unsigned long long d;
    asm("fma.rn.f32x2 %0, %1, %2, %3;" : "=l"(d) : "l"(a), "l"(b), "l"(c));
    return d;
}
__device__ __forceinline__ unsigned long long dup2(float v) {
    unsigned long long d;
    asm("mov.b64 %0, {%1, %1};" : "=l"(d) : "f"(v));
    return d;
}
__device__ __forceinline__ void unpk2(unsigned long long a, float& lo, float& hi) {
    asm("mov.b64 {%0, %1}, %2;" : "=f"(lo), "=f"(hi) : "l"(a));
}

// top-2 update: candidates arrive in ascending k, strict > keeps first index
__device__ __forceinline__ void top2(float s, int k,
                                     float& bv, int& bi, float& sv, int& si) {
    if (s > bv) { sv = bv; si = bi; bv = s; bi = k; }
    else if (s > sv) { sv = s; si = k; }
}

__global__ __launch_bounds__(THREADS, 1)
void vq_kernel(const float* __restrict__ x, const float* __restrict__ cb,
               float* __restrict__ out, int write_idx)
{
    extern __shared__ float sm[];
    float* cs     = sm;                       // [512][65]  codebook (col 64 = 0.5*||c||^2)
    float* xs     = cs + CS_FLOATS;           // [64][64]   x tile, xs[c][w]
    float* rv     = xs + XS_FLOATS;           // [64][17]   best vals
    float* r2v    = rv + RED_FLOATS;          // [64][17]   second vals
    int*   ri     = (int*)(r2v + RED_FLOATS); // [64][17]   best idx
    int*   r2i    = ri + RED_FLOATS;          // [64][17]   second idx
    int*   idx_sh = r2i + RED_FLOATS;         // [64]

    const int tid = threadIdx.x;

    // ---- load codebook (once per persistent CTA) ----
    for (int i = tid; i < KCODES*DCH; i += THREADS) {
        int k = i >> 6, c = i & 63;
        cs[k*CSTR + c] = cb[i];
    }
    __syncthreads();
    for (int k = tid; k < KCODES; k += THREADS) {
        const float* row = cs + k*CSTR;
        float s = 0.f;
        #pragma unroll
        for (int c = 0; c < DCH; c++) s += row[c]*row[c];
        cs[k*CSTR + 64] = 0.5f * s;
    }

    const int py = tid >> 4;   // 0..15 : position group (4 positions each)
    const int kx = tid & 15;   // 0..15 : code column (k == kx mod 16)

    for (int tile = blockIdx.x; tile < NTILES; tile += gridDim.x) {
        const int b = tile >> 6;
        const int h = tile & 63;
        __syncthreads();   // covers cs init & previous tile's epilogue

        // ---- stage x tile: xs[c][w] = x[b,c,h,w] ----
        for (int i4 = tid; i4 < (DCH*WW)/4; i4 += THREADS) {
            int c  = i4 >> 4;
            int w4 = i4 & 15;
            float4 v = *(const float4*)(x + ((((size_t)b*DCH + c)*HH + h)*WW) + w4*4);
            *(float4*)(xs + c*WW + w4*4) = v;
        }
        __syncthreads();

        // ---- score s = x.c - 0.5||c||^2, track per-thread top-2 per position ----
        float bv0=-3.4e38f,bv1=-3.4e38f,bv2=-3.4e38f,bv3=-3.4e38f;
        float sv0=-3.4e38f,sv1=-3.4e38f,sv2=-3.4e38f,sv3=-3.4e38f;
        int bi0=0,bi1=0,bi2=0,bi3=0, si0=0,si1=0,si2=0,si3=0;

        for (int chunk = 0; chunk < 4; chunk++) {
            const int kbase = chunk*128 + kx;
            const float* crow[8];
            #pragma unroll
            for (int j = 0; j < 8; j++) crow[j] = cs + (kbase + 16*j)*CSTR;

            unsigned long long a0[8], a1[8];
            #pragma unroll
            for (int j = 0; j < 8; j++) { a0[j] = 0ull; a1[j] = 0ull; }

            #pragma unroll 8
            for (int c = 0; c < DCH; c++) {
                unsigned long long xp0 = *(const unsigned long long*)(xs + c*WW + py*4);
                unsigned long long xp1 = *(const unsigned long long*)(xs + c*WW + py*4 + 2);
                #pragma unroll
                for (int j = 0; j < 8; j++) {
                    unsigned long long vv = dup2(crow[j][c]);
                    a0[j] = ffma2(xp0, vv, a0[j]);
                    a1[j] = ffma2(xp1, vv, a1[j]);
                }
            }

            #pragma unroll
            for (int j = 0; j < 8; j++) {
                const int k  = kbase + 16*j;
                const float hn = crow[j][64];
                float s0, s1, s2, s3;
                unpk2(a0[j], s0, s1);
                unpk2(a1[j], s2, s3);
                s0 -= hn; s1 -= hn; s2 -= hn; s3 -= hn;
                top2(s0, k, bv0, bi0, sv0, si0);
                top2(s1, k, bv1, bi1, sv1, si1);
                top2(s2, k, bv2, bi2, sv2, si2);
                top2(s3, k, bv3, bi3, sv3, si3);
            }
        }

        // ---- deposit per-thread top-2 ----
        {
            int p = py*4;
            rv [(p+0)*RED_STR + kx] = bv0; ri [(p+0)*RED_STR + kx] = bi0;
            r2v[(p+0)*RED_STR + kx] = sv0; r2i[(p+0)*RED_STR + kx] = si0;
            rv [(p+1)*RED_STR + kx] = bv1; ri [(p+1)*RED_STR + kx] = bi1;
            r2v[(p+1)*RED_STR + kx] = sv1; r2i[(p+1)*RED_STR + kx] = si1;
            rv [(p+2)*RED_STR + kx] = bv2; ri [(p+2)*RED_STR + kx] = bi2;
            r2v[(p+2)*RED_STR + kx] = sv2; r2i[(p+2)*RED_STR + kx] = si2;
            rv [(p+3)*RED_STR + kx] = bv3; ri [(p+3)*RED_STR + kx] = bi3;
            r2v[(p+3)*RED_STR + kx] = sv3; r2i[(p+3)*RED_STR + kx] = si3;
        }
        __syncthreads();

        // ---- global top-2 merge over 32 candidates, then exact refinement ----
        if (tid < WW) {
            const int p = tid;
            float bv = -3.4e38f, sv = -3.4e38f;
            int   bi = 0x7fffffff, si = 0x7fffffff;
            #pragma unroll
            for (int q = 0; q < 32; q++) {
                float v = (q < 16) ? rv [p*RED_STR + q] : r2v[p*RED_STR + (q-16)];
                int   i = (q < 16) ? ri [p*RED_STR + q] : r2i[p*RED_STR + (q-16)];
                if (v > bv || (v == bv && i < bi)) {
                    sv = bv; si = bi; bv = v; bi = i;
                } else if ((v > sv || (v == sv && i < si)) && i != bi) {
                    sv = v; si = i;
                }
            }
            // near-tie: arbitrate exactly in double precision
            if (bv - sv < MARGIN && si != bi) {
                const float* cbb = cs + bi*CSTR;
                const float* cbs = cs + si*CSTR;
                double db = 0.0, ds = 0.0;
                for (int c = 0; c < DCH; c++) {
                    double xv = (double)xs[c*WW + p];
                    double e1 = xv - (double)cbb[c];
                    double e2 = xv - (double)cbs[c];
                    db += e1*e1;
                    ds += e2*e2;
                }
                if (ds < db || (ds == db && si < bi)) bi = si;
            }
            idx_sh[p] = bi;
        }
        __syncthreads();

        // ---- epilogue: codes[b,c,h,w] = cs[idx[w]][c] ----
        for (int i4 = tid; i4 < (DCH*WW)/4; i4 += THREADS) {
            int c  = i4 >> 4;
            int w  = (i4 & 15) * 4;
            float4 v;
            v.x = cs[idx_sh[w+0]*CSTR + c];
            v.y = cs[idx_sh[w+1]*CSTR + c];
            v.z = cs[idx_sh[w+2]*CSTR + c];
            v.w = cs[idx_sh[w+3]*CSTR + c];
            *(float4*)(out + (((size_t)b*DCH + c)*HH + h)*WW + w) = v;
        }
        if (write_idx && tid < WW) {
            out[CODES_ELEMS + ((size_t)b*HH + h)*WW + tid] = (float)idx_sh[tid];
        }
    }
}

extern "C" void kernel_launch(void* const* d_in, const int* in_sizes, int n_in,
                              void* d_out, int out_size)
{
    const float* x  = (const float*)d_in[0];
    const float* cb = (const float*)d_in[1];
    float* out = (float*)d_out;

    int write_idx = ((size_t)out_size >= CODES_ELEMS + IDX_ELEMS) ? 1 : 0;

    int dev = 0;
    cudaGetDevice(&dev);
    int sms = 0;
    cudaDeviceGetAttribute(&sms, cudaDevAttrMultiProcessorCount, dev);
    if (sms <= 0) sms = 148;
    if (sms > NTILES) sms = NTILES;

    cudaFuncSetAttribute(vq_kernel, cudaFuncAttributeMaxDynamicSharedMemorySize,
                         (int)SMEM_BYTES);
    vq_kernel<<<sms, THREADS, SMEM_BYTES>>>(x, cb, out, write_idx);
}

// round 7
// speedup vs baseline: 1.3984x; 1.3984x over previous
#include <cuda_runtime.h>
#include <cstddef>

// VQ nearest-neighbor quantization (exact argmin via fp64 near-tie refinement)
// x: [32,64,64,64] f32 (B,C,H,W), codebook: [512,64] f32
// out: codes [B,C,H,W] f32 (8388608) followed by indices [B,H,W] as f32 (131072)

#define KCODES 512
#define DCH    64
#define BATCH  32
#define HH     64
#define WW     64
#define THREADS 512
#define POS     128              // positions per tile = 2 h-rows
#define NTILES  (BATCH*(HH/2))   // 1024 tile-pairs
#define CSTRT   514              // transposed codebook row stride (words per channel)
#define RED_STR 17
#define MARGIN  1e-2f            // near-tie refinement margin (score units)

#define CODES_ELEMS ((size_t)BATCH*DCH*HH*WW)   // 8388608
#define IDX_ELEMS   ((size_t)BATCH*HH*WW)       // 131072

// shared layout (floats)
#define CST_FLOATS (DCH*CSTRT)          // 32896  codebook transposed [c][k], pairs adjacent
#define XS_FLOATS  (DCH*POS)            // 8192   x tile [c][p]
#define HN_FLOATS  (KCODES)             // 512    0.5*||c_k||^2
#define RED_FLOATS (POS*RED_STR)        // 2176
#define SMEM_BYTES ((CST_FLOATS + XS_FLOATS + HN_FLOATS + 4*RED_FLOATS + POS)*4)

__device__ __forceinline__ unsigned long long ffma2(unsigned long long a,
                                                    unsigned long long b,
                                                    unsigned long long c) {
    unsigned long long d;
    asm("fma.rn.f32x2 %0, %1, %2, %3;" : "=l"(d) : "l"(a), "l"(b), "l"(c));
    return d;
}
__device__ __forceinline__ unsigned long long dup2(float v) {
    unsigned long long d;
    asm("mov.b64 %0, {%1, %1};" : "=l"(d) : "f"(v));
    return d;
}
__device__ __forceinline__ void unpk2(unsigned long long a, float& lo, float& hi) {
    asm("mov.b64 {%0, %1}, %2;" : "=f"(lo), "=f"(hi) : "l"(a));
}

// top-2 update: candidates arrive in ascending k, strict > keeps first index
__device__ __forceinline__ void top2(float s, int k,
                                     float& bv, int& bi, float& sv, int& si) {
    if (s > bv) { sv = bv; si = bi; bv = s; bi = k; }
    else if (s > sv) { sv = s; si = k; }
}

__global__ __launch_bounds__(THREADS, 1)
void vq_kernel(const float* __restrict__ x, const float* __restrict__ cb,
               float* __restrict__ out, int write_idx)
{
    extern __shared__ float sm[];
    float* cs_t   = sm;                       // [64][514]  codebook transposed [c][k]
    float* xs     = cs_t + CST_FLOATS;        // [64][128]  x tile [c][p]
    float* hn     = xs + XS_FLOATS;           // [512]      0.5*||c||^2
    float* rv     = hn + HN_FLOATS;           // [128][17]  best vals
    float* r2v    = rv + RED_FLOATS;          // [128][17]  second vals
    int*   ri     = (int*)(r2v + RED_FLOATS); // [128][17]  best idx
    int*   r2i    = ri + RED_FLOATS;          // [128][17]  second idx
    int*   idx_sh = r2i + RED_FLOATS;         // [128]

    const int tid = threadIdx.x;

    // ---- load codebook transposed (once per persistent CTA) ----
    // read cb[k*64+c] coalesced, write cs_t[c*514 + k] (2-way bank conflict, one-time)
    for (int i = tid; i < KCODES*DCH; i += THREADS) {
        int k = i >> 6, c = i & 63;
        cs_t[c*CSTRT + k] = cb[i];
    }
    __syncthreads();
    // half-norms (per-k column sums; conflict-free: banks = k mod 32)
    if (tid < KCODES) {
        float s = 0.f;
        #pragma unroll
        for (int c = 0; c < DCH; c++) {
            float v = cs_t[c*CSTRT + tid];
            s += v*v;
        }
        hn[tid] = 0.5f * s;
    }

    const int kx = tid & 15;   // 0..15 : code-pair column
    const int pg = tid >> 4;   // 0..31 : position group (4 positions each)

    for (int tile = blockIdx.x; tile < NTILES; tile += gridDim.x) {
        const int b  = tile >> 5;        // 0..31
        const int h0 = (tile & 31) * 2;  // 2 rows: h0, h0+1
        __syncthreads();   // protects hn init & previous tile's epilogue reads

        // ---- stage x tile: xs[c][p], p = hl*64 + w ----
        for (int i4 = tid; i4 < (DCH*POS)/4; i4 += THREADS) {
            int c  = i4 >> 5;          // 0..63
            int p4 = i4 & 31;          // 0..31
            int p  = p4 * 4;
            int hl = p >> 6, w = p & 63;
            float4 v = *(const float4*)(x + ((((size_t)b*DCH + c)*HH + h0 + hl)*WW) + w);
            *(float4*)(xs + c*POS + p) = v;
        }
        __syncthreads();

        // ---- score s = x.c - 0.5||c||^2 over 512 codes, per-thread top-2 ----
        float bv[4], sv[4];
        int   bi[4], si[4];
        #pragma unroll
        for (int i = 0; i < 4; i++) { bv[i] = -3.4e38f; sv[i] = -3.4e38f; bi[i] = 0; si[i] = 0; }

        for (int chunk = 0; chunk < 4; chunk++) {
            const int pj0 = chunk*64 + kx;   // pair index base; pairs pj0 + 16*j
            unsigned long long acc[4][4];
            #pragma unroll
            for (int i = 0; i < 4; i++)
                #pragma unroll
                for (int j = 0; j < 4; j++) acc[i][j] = 0ull;

            const float* xrow = xs + pg*4;
            const float* crow = cs_t + pj0*2;

            #pragma unroll 8
            for (int c = 0; c < DCH; c++) {
                float4 xq = *(const float4*)(xrow + c*POS);
                unsigned long long xd0 = dup2(xq.x);
                unsigned long long xd1 = dup2(xq.y);
                unsigned long long xd2 = dup2(xq.z);
                unsigned long long xd3 = dup2(xq.w);
                #pragma unroll
                for (int j = 0; j < 4; j++) {
                    unsigned long long cp =
                        *(const unsigned long long*)(crow + c*CSTRT + j*32);
                    acc[0][j] = ffma2(xd0, cp, acc[0][j]);
                    acc[1][j] = ffma2(xd1, cp, acc[1][j]);
                    acc[2][j] = ffma2(xd2, cp, acc[2][j]);
                    acc[3][j] = ffma2(xd3, cp, acc[3][j]);
                }
            }

            #pragma unroll
            for (int j = 0; j < 4; j++) {
                const int k0 = (pj0 + 16*j) * 2;
                float2 hnp = *(const float2*)(hn + k0);
                #pragma unroll
                for (int i = 0; i < 4; i++) {
                    float slo, shi;
                    unpk2(acc[i][j], slo, shi);
                    slo -= hnp.x; shi -= hnp.y;
                    top2(slo, k0,     bv[i], bi[i], sv[i], si[i]);
                    top2(shi, k0 + 1, bv[i], bi[i], sv[i], si[i]);
                }
            }
        }

        // ---- deposit per-thread top-2 ----
        #pragma unroll
        for (int i = 0; i < 4; i++) {
            int p = pg*4 + i;
            rv [p*RED_STR + kx] = bv[i];  ri [p*RED_STR + kx] = bi[i];
            r2v[p*RED_STR + kx] = sv[i];  r2i[p*RED_STR + kx] = si[i];
        }
        __syncthreads();

        // ---- global top-2 merge over 32 candidates + exact fp64 refinement ----
        if (tid < POS) {
            const int p = tid;
            float gbv = -3.4e38f, gsv = -3.4e38f;
            int   gbi = 0x7fffffff, gsi = 0x7fffffff;
            #pragma unroll
            for (int q = 0; q < 32; q++) {
                float v = (q < 16) ? rv [p*RED_STR + q] : r2v[p*RED_STR + (q-16)];
                int   i = (q < 16) ? ri [p*RED_STR + q] : r2i[p*RED_STR + (q-16)];
                if (v > gbv || (v == gbv && i < gbi)) {
                    gsv = gbv; gsi = gbi; gbv = v; gbi = i;
                } else if ((v > gsv || (v == gsv && i < gsi)) && i != gbi) {
                    gsv = v; gsi = i;
                }
            }
            if (gbv - gsv < MARGIN && gsi != gbi) {
                double db = 0.0, ds = 0.0;
                for (int c = 0; c < DCH; c++) {
                    double xv = (double)xs[c*POS + p];
                    double e1 = xv - (double)cs_t[c*CSTRT + gbi];
                    double e2 = xv - (double)cs_t[c*CSTRT + gsi];
                    db += e1*e1;
                    ds += e2*e2;
                }
                if (ds < db || (ds == db && gsi < gbi)) gbi = gsi;
            }
            idx_sh[p] = gbi;
        }
        __syncthreads();

        // ---- epilogue: codes[b,c,h,w] = codebook[idx[p]][c] ----
        for (int i4 = tid; i4 < (DCH*POS)/4; i4 += THREADS) {
            int c  = i4 >> 5;
            int p  = (i4 & 31) * 4;
            int hl = p >> 6, w = p & 63;
            const float* row = cs_t + c*CSTRT;
            float4 v;
            v.x = row[idx_sh[p+0]];
            v.y = row[idx_sh[p+1]];
            v.z = row[idx_sh[p+2]];
            v.w = row[idx_sh[p+3]];
            *(float4*)(out + (((size_t)b*DCH + c)*HH + h0 + hl)*WW + w) = v;
        }
        if (write_idx && tid < POS) {
            int hl = tid >> 6, w = tid & 63;
            out[CODES_ELEMS + ((size_t)b*HH + h0 + hl)*WW + w] = (float)idx_sh[tid];
        }
    }
}

extern "C" void kernel_launch(void* const* d_in, const int* in_sizes, int n_in,
                              void* d_out, int out_size)
{
    const float* x  = (const float*)d_in[0];
    const float* cb = (const float*)d_in[1];
    float* out = (float*)d_out;

    int write_idx = ((size_t)out_size >= CODES_ELEMS + IDX_ELEMS) ? 1 : 0;

    int dev = 0;
    cudaGetDevice(&dev);
    int sms = 0;
    cudaDeviceGetAttribute(&sms, cudaDevAttrMultiProcessorCount, dev);
    if (sms <= 0) sms = 148;
    if (sms > NTILES) sms = NTILES;

    cudaFuncSetAttribute(vq_kernel, cudaFuncAttributeMaxDynamicSharedMemorySize,
                         (int)SMEM_BYTES);
    vq_kernel<<<sms, THREADS, SMEM_BYTES>>>(x, cb, out, write_idx);
}

// round 8
// speedup vs baseline: 1.5534x; 1.1108x over previous
#include <cuda_runtime.h>
#include <cstddef>

// VQ nearest-neighbor quantization (exact argmin via fp64 near-tie refinement)
// x: [32,64,64,64] f32 (B,C,H,W), codebook: [512,64] f32
// out: codes [B,C,H,W] f32 (8388608) followed by indices [B,H,W] as f32 (131072)

#define KCODES 512
#define DCH    64
#define BATCH  32
#define HH     64
#define WW     64
#define THREADS 512
#define POS     128              // positions per tile = 2 h-rows
#define NTILES  (BATCH*(HH/2))   // 1024
#define CSTRT   520              // transposed codebook row stride (16B-aligned rows)
#define BIAS    512.0f           // score bias: all scores positive -> int-monotone bits
#define MARGIN  0.05f            // near-tie refinement margin (score units)

#define CODES_ELEMS ((size_t)BATCH*DCH*HH*WW)   // 8388608
#define IDX_ELEMS   ((size_t)BATCH*HH*WW)       // 131072

// shared layout (floats)
#define CST_FLOATS (DCH*CSTRT)          // 33280  codebook transposed [c][k]
#define XS_FLOATS  (DCH*POS)            // 8192   x tile [c][p]
#define HB_FLOATS  (KCODES)             // 512    BIAS - 0.5*||c_k||^2
#define SMEM_BYTES ((CST_FLOATS + XS_FLOATS + HB_FLOATS + POS)*4)

typedef unsigned long long ull;
typedef unsigned int uint;

__device__ __forceinline__ ull ffma2(ull a, ull b, ull c) {
    ull d;
    asm("fma.rn.f32x2 %0, %1, %2, %3;" : "=l"(d) : "l"(a), "l"(b), "l"(c));
    return d;
}
__device__ __forceinline__ ull dup2(float v) {
    ull d;
    asm("mov.b64 %0, {%1, %1};" : "=l"(d) : "f"(v));
    return d;
}
__device__ __forceinline__ void unpk2u(ull a, uint& lo, uint& hi) {
    asm("mov.b64 {%0, %1}, %2;" : "=r"(lo), "=r"(hi) : "l"(a));
}

// decode quantized key back to (approx value, exact code index)
__device__ __forceinline__ void key_decode(uint key, int kx, float& v, int& k) {
    int j5    = 31 - (int)(key & 31u);
    int chunk = j5 >> 3;
    int rr    = j5 & 7;
    k = chunk*128 + 4*kx + ((rr >> 2) << 6) + (rr & 3);
    v = __uint_as_float(key & ~31u) - BIAS;
}

__global__ __launch_bounds__(THREADS, 1)
void vq_kernel(const float* __restrict__ x, const float* __restrict__ cb,
               float* __restrict__ out, int write_idx)
{
    extern __shared__ float sm[];
    float* cs_t   = sm;                   // [64][520]  codebook transposed [c][k]
    float* xs     = cs_t + CST_FLOATS;    // [64][128]  x tile [c][p]
    float* hb     = xs + XS_FLOATS;       // [512]      BIAS - 0.5||c||^2
    int*   idx_sh = (int*)(hb + HB_FLOATS); // [128]

    const int tid = threadIdx.x;

    // ---- load codebook transposed (once per persistent CTA) ----
    for (int i = tid; i < KCODES*DCH; i += THREADS) {
        int k = i >> 6, c = i & 63;
        cs_t[c*CSTRT + k] = cb[i];
    }
    __syncthreads();
    // biased half-norms (conflict-free column sums)
    if (tid < KCODES) {
        float s = 0.f;
        #pragma unroll
        for (int c = 0; c < DCH; c++) {
            float v = cs_t[c*CSTRT + tid];
            s += v*v;
        }
        hb[tid] = BIAS - 0.5f*s;
    }

    const int kx = tid & 15;   // 0..15 : code column (quads 4kx.. / 4(kx+16)..)
    const int pg = tid >> 4;   // 0..31 : position group (4 positions each)

    for (int tile = blockIdx.x; tile < NTILES; tile += gridDim.x) {
        const int b  = tile >> 5;
        const int h0 = (tile & 31) * 2;
        __syncthreads();   // protects hb init & previous tile's shared reads

        // ---- stage x tile: xs[c][p], p = hl*64 + w ----
        for (int i4 = tid; i4 < (DCH*POS)/4; i4 += THREADS) {
            int c  = i4 >> 5;
            int p  = (i4 & 31) * 4;
            int hl = p >> 6, w = p & 63;
            float4 v = *(const float4*)(x + ((((size_t)b*DCH + c)*HH + h0 + hl)*WW) + w);
            *(float4*)(xs + c*POS + p) = v;
        }
        __syncthreads();

        // ---- biased scores + predicate-free quantized top-2 ----
        uint bK[4] = {0u,0u,0u,0u};
        uint sK[4] = {0u,0u,0u,0u};

        const float* xrow = xs + pg*4;

        #pragma unroll
        for (int chunk = 0; chunk < 4; chunk++) {
            // init accumulators to (BIAS - hn) pairs
            const float* hq = hb + chunk*128 + 4*kx;
            ulonglong2 hv0 = *(const ulonglong2*)hq;         // pairs (4kx,4kx+1),(4kx+2,4kx+3)
            ulonglong2 hv1 = *(const ulonglong2*)(hq + 64);  // quad kx+16
            ull acc[4][4];
            #pragma unroll
            for (int i = 0; i < 4; i++) {
                acc[i][0] = hv0.x; acc[i][1] = hv0.y;
                acc[i][2] = hv1.x; acc[i][3] = hv1.y;
            }

            const float* crow = cs_t + chunk*128 + 4*kx;

            #pragma unroll 8
            for (int c = 0; c < DCH; c++) {
                float4 xq = *(const float4*)(xrow + c*POS);
                ull xd0 = dup2(xq.x), xd1 = dup2(xq.y);
                ull xd2 = dup2(xq.z), xd3 = dup2(xq.w);
                ulonglong2 q0 = *(const ulonglong2*)(crow + c*CSTRT);       // codes 4kx..+3
                ulonglong2 q1 = *(const ulonglong2*)(crow + c*CSTRT + 64);  // codes 4(kx+16)..+3
                acc[0][0] = ffma2(xd0, q0.x, acc[0][0]);
                acc[1][0] = ffma2(xd1, q0.x, acc[1][0]);
                acc[2][0] = ffma2(xd2, q0.x, acc[2][0]);
                acc[3][0] = ffma2(xd3, q0.x, acc[3][0]);
                acc[0][1] = ffma2(xd0, q0.y, acc[0][1]);
                acc[1][1] = ffma2(xd1, q0.y, acc[1][1]);
                acc[2][1] = ffma2(xd2, q0.y, acc[2][1]);
                acc[3][1] = ffma2(xd3, q0.y, acc[3][1]);
                acc[0][2] = ffma2(xd0, q1.x, acc[0][2]);
                acc[1][2] = ffma2(xd1, q1.x, acc[1][2]);
                acc[2][2] = ffma2(xd2, q1.x, acc[2][2]);
                acc[3][2] = ffma2(xd3, q1.x, acc[3][2]);
                acc[0][3] = ffma2(xd0, q1.y, acc[0][3]);
                acc[1][3] = ffma2(xd1, q1.y, acc[1][3]);
                acc[2][3] = ffma2(xd2, q1.y, acc[2][3]);
                acc[3][3] = ffma2(xd3, q1.y, acc[3][3]);
            }

            // chunk epilogue: quantized keys + IMNMX top-2 (no predicates)
            #pragma unroll
            for (int pr = 0; pr < 4; pr++) {
                const uint jrevL = 31u - (uint)(chunk*8 + pr*2 + 0);
                const uint jrevH = 31u - (uint)(chunk*8 + pr*2 + 1);
                #pragma unroll
                for (int i = 0; i < 4; i++) {
                    uint lo, hi;
                    unpk2u(acc[i][pr], lo, hi);
                    uint keyL = (lo & ~31u) | jrevL;
                    uint keyH = (hi & ~31u) | jrevH;
                    sK[i] = umax(sK[i], umin(bK[i], keyL));
                    bK[i] = umax(bK[i], keyL);
                    sK[i] = umax(sK[i], umin(bK[i], keyH));
                    bK[i] = umax(bK[i], keyH);
                }
            }
        }

        // ---- decode per-thread top-2, butterfly-merge across 16 kx lanes ----
        float vb[4], vs[4];
        int   kb[4], ks[4];
        #pragma unroll
        for (int i = 0; i < 4; i++) {
            key_decode(bK[i], kx, vb[i], kb[i]);
            key_decode(sK[i], kx, vs[i], ks[i]);
        }
        #pragma unroll
        for (int m = 1; m < 16; m <<= 1) {
            #pragma unroll
            for (int i = 0; i < 4; i++) {
                float ovb = __shfl_xor_sync(0xFFFFFFFFu, vb[i], m);
                int   okb = __shfl_xor_sync(0xFFFFFFFFu, kb[i], m);
                float ovs = __shfl_xor_sync(0xFFFFFFFFu, vs[i], m);
                int   oks = __shfl_xor_sync(0xFFFFFFFFu, ks[i], m);
                bool ow = (ovb > vb[i]) || (ovb == vb[i] && okb < kb[i]);
                float lv = ow ? vb[i] : ovb;  int lk = ow ? kb[i] : okb;  // losing best
                float wv = ow ? ovs : vs[i];  int wk = ow ? oks : ks[i];  // winner's 2nd
                if (ow) { vb[i] = ovb; kb[i] = okb; }
                bool sw = (lv > wv) || (lv == wv && lk < wk);
                vs[i] = sw ? lv : wv;  ks[i] = sw ? lk : wk;
            }
        }

        // ---- near-tie exact fp64 arbitration + index write ----
        {
            int g = tid & 15;
            if (g < 4) {
                int p  = pg*4 + g;
                int bi = kb[g], si = ks[g];
                if (vb[g] - vs[g] < MARGIN && si != bi) {
                    double db = 0.0, ds = 0.0;
                    for (int c = 0; c < DCH; c++) {
                        double xv = (double)xs[c*POS + p];
                        double e1 = xv - (double)cs_t[c*CSTRT + bi];
                        double e2 = xv - (double)cs_t[c*CSTRT + si];
                        db += e1*e1;
                        ds += e2*e2;
                    }
                    if (ds < db || (ds == db && si < bi)) bi = si;
                }
                idx_sh[p] = bi;
            }
        }
        __syncthreads();

        // ---- epilogue: codes[b,c,h,w] = codebook[idx[p]][c] ----
        for (int i4 = tid; i4 < (DCH*POS)/4; i4 += THREADS) {
            int c  = i4 >> 5;
            int p  = (i4 & 31) * 4;
            int hl = p >> 6, w = p & 63;
            const float* row = cs_t + c*CSTRT;
            float4 v;
            v.x = row[idx_sh[p+0]];
            v.y = row[idx_sh[p+1]];
            v.z = row[idx_sh[p+2]];
            v.w = row[idx_sh[p+3]];
            *(float4*)(out + (((size_t)b*DCH + c)*HH + h0 + hl)*WW + w) = v;
        }
        if (write_idx && tid < POS) {
            int hl = tid >> 6, w = tid & 63;
            out[CODES_ELEMS + ((size_t)b*HH + h0 + hl)*WW + w] = (float)idx_sh[tid];
        }
    }
}

extern "C" void kernel_launch(void* const* d_in, const int* in_sizes, int n_in,
                              void* d_out, int out_size)
{
    const float* x  = (const float*)d_in[0];
    const float* cb = (const float*)d_in[1];
    float* out = (float*)d_out;

    int write_idx = ((size_t)out_size >= CODES_ELEMS + IDX_ELEMS) ? 1 : 0;

    int dev = 0;
    cudaGetDevice(&dev);
    int sms = 0;
    cudaDeviceGetAttribute(&sms, cudaDevAttrMultiProcessorCount, dev);
    if (sms <= 0) sms = 148;
    if (sms > NTILES) sms = NTILES;

    cudaFuncSetAttribute(vq_kernel, cudaFuncAttributeMaxDynamicSharedMemorySize,
                         (int)SMEM_BYTES);
    vq_kernel<<<sms, THREADS, SMEM_BYTES>>>(x, cb, out, write_idx);
}

// round 10
// speedup vs baseline: 1.9103x; 1.2298x over previous
#include <cuda_runtime.h>
#include <cuda_bf16.h>
#include <cstdint>
#include <cstddef>

// VQ nearest-neighbor quantization via mma.sync bf16 3-term split,
// exact argmin via fp64 near-tie refinement.
// x: [32,64,64,64] f32 (B,C,H,W), codebook: [512,64] f32
// out: codes [B,C,H,W] f32 (8388608) then indices [B,H,W] as f32 (131072)

#define KCODES 512
#define DCH    64
#define BATCH  32
#define HH     64
#define WW     64
#define THREADS 512
#define POS     128
#define NTILES  (BATCH*(HH/2))   // 1024
#define BIAS    512.0f
#define MARGIN  0.05f
#define XSTR    68               // xs row stride (floats), 16B-aligned rows

#define CODES_ELEMS ((size_t)BATCH*DCH*HH*WW)
#define IDX_ELEMS   ((size_t)BATCH*HH*WW)

// ---- smem byte offsets from 1024-aligned base ----
#define A_HI_OFF 0            // [128][128B] bf16 SW128
#define A_LO_OFF 16384
#define B_HI_OFF 32768        // [512][128B] bf16 SW128
#define B_LO_OFF 98304
#define XS_OFF   163840       // float[128][68] exact x tile
#define HB_OFF   198656       // float[512] BIAS - 0.5||c||^2
#define VB_OFF   200704       // float[128][4]
#define VS_OFF   202752
#define KB_OFF   204800       // int[128][4]
#define KS_OFF   206848
#define IDXS_OFF 208896       // int[128]
#define SMEM_BYTES (209408 + 1024)

#define SW(o) ((o) ^ (((o) >> 3) & 0x70))

typedef uint32_t u32;

static __device__ __forceinline__ u32 smem_u32(const void* p) {
    u32 a;
    asm("{ .reg .u64 t; cvta.to.shared.u64 t, %1; cvt.u32.u64 %0, t; }" : "=r"(a) : "l"(p));
    return a;
}

#define LDSM_X4(r0,r1,r2,r3, addr) \
    asm volatile("ldmatrix.sync.aligned.m8n8.x4.shared.b16 {%0,%1,%2,%3}, [%4];" \
        : "=r"(r0),"=r"(r1),"=r"(r2),"=r"(r3) : "r"(addr))

#define MMA16816(d, a, b0, b1) \
    asm volatile("mma.sync.aligned.m16n8k16.row.col.f32.bf16.bf16.f32 " \
        "{%0,%1,%2,%3}, {%4,%5,%6,%7}, {%8,%9}, {%0,%1,%2,%3};" \
        : "+f"((d)[0]),"+f"((d)[1]),"+f"((d)[2]),"+f"((d)[3]) \
        : "r"((a)[0]),"r"((a)[1]),"r"((a)[2]),"r"((a)[3]), "r"(b0),"r"(b1))

__global__ __launch_bounds__(THREADS, 1)
void vq_kernel(const float* __restrict__ x, const float* __restrict__ cb,
               float* __restrict__ out, int write_idx)
{
    extern __shared__ char smraw[];
    const u32 sb0 = smem_u32(smraw);
    const u32 sb  = (sb0 + 1023u) & ~1023u;
    char* base = smraw + (sb - sb0);

    float* xs   = (float*)(base + XS_OFF);
    float* hb   = (float*)(base + HB_OFF);
    float* vb4  = (float*)(base + VB_OFF);
    float* vs4  = (float*)(base + VS_OFF);
    int*   kb4  = (int*)  (base + KB_OFF);
    int*   ks4  = (int*)  (base + KS_OFF);
    int*   idxs = (int*)  (base + IDXS_OFF);

    const int tid  = threadIdx.x;
    const int wid  = tid >> 5;
    const int lane = tid & 31;
    const int wm   = wid & 3;    // M group: positions 32*wm..+31
    const int wn   = wid >> 2;   // N group: codes 128*wn..+127
    const int q    = lane & 3;   // column pair within C frag

    // per-lane ldmatrix geometry (non-trans for both A and B)
    const int a_row = (lane & 7) + ((lane >> 3) & 1) * 8;
    const int a_kb  = (lane >> 4) & 1;
    const int b_row = (lane & 7) + ((lane >> 4) & 1) * 8;
    const int b_kb  = (lane >> 3) & 1;
    const u32 xorL  = (u32)((lane & 7) << 4);

    // ---- one-time: codebook -> bf16 hi/lo swizzled SMEM (coalesced read) ----
    for (int it = 0; it < 16; it++) {
        int idx = tid + it * THREADS;        // 8192 items: (k, cgroup)
        int k  = idx >> 4;
        int c0 = (idx & 15) * 4;
        float4 v = *(const float4*)(cb + (size_t)k * DCH + c0);
        u32 hi0, hi1, lo0, lo1;
        {
            __nv_bfloat16 hx = __float2bfloat16(v.x), hy = __float2bfloat16(v.y);
            __nv_bfloat16 hz = __float2bfloat16(v.z), hw = __float2bfloat16(v.w);
            hi0 = (u32)__bfloat16_as_ushort(hx) | ((u32)__bfloat16_as_ushort(hy) << 16);
            hi1 = (u32)__bfloat16_as_ushort(hz) | ((u32)__bfloat16_as_ushort(hw) << 16);
            __nv_bfloat16 lx = __float2bfloat16(v.x - __bfloat162float(hx));
            __nv_bfloat16 ly = __float2bfloat16(v.y - __bfloat162float(hy));
            __nv_bfloat16 lz = __float2bfloat16(v.z - __bfloat162float(hz));
            __nv_bfloat16 lw = __float2bfloat16(v.w - __bfloat162float(hw));
            lo0 = (u32)__bfloat16_as_ushort(lx) | ((u32)__bfloat16_as_ushort(ly) << 16);
            lo1 = (u32)__bfloat16_as_ushort(lz) | ((u32)__bfloat16_as_ushort(lw) << 16);
        }
        u32 o = (u32)(k * 128) + (u32)((c0 * 2) ^ ((k & 7) << 4));
        *(uint2*)(base + B_HI_OFF + o) = make_uint2(hi0, hi1);
        *(uint2*)(base + B_LO_OFF + o) = make_uint2(lo0, lo1);
    }
    if (tid < KCODES) {
        float s = 0.f;
        #pragma unroll
        for (int c = 0; c < DCH; c++) { float v = cb[(size_t)tid * DCH + c]; s += v * v; }
        hb[tid] = BIAS - 0.5f * s;
    }
    __syncthreads();

    for (int tile = blockIdx.x; tile < NTILES; tile += gridDim.x) {
        const int b  = tile >> 5;
        const int h0 = (tile & 31) * 2;
        __syncthreads();  // previous tile's smem reads complete

        // ---- stage pass 1: global -> exact xs (coalesced) ----
        for (int it = 0; it < 16; it++) {
            int i = tid + it * THREADS;     // 8192 = 64c * 128p
            int c = i >> 7, p = i & 127;
            int hl = p >> 6, w = p & 63;
            xs[p * XSTR + c] = x[((((size_t)b * DCH + c) * HH) + h0 + hl) * WW + w];
        }
        __syncthreads();

        // ---- stage pass 2: xs -> bf16 hi/lo swizzled A (conflict-free) ----
        for (int it = 0; it < 4; it++) {
            int idx = tid + it * THREADS;    // 2048 = 128p * 16 cgroups
            int p  = idx >> 4;
            int c0 = (idx & 15) * 4;
            float4 v = *(const float4*)(xs + p * XSTR + c0);
            u32 hi0, hi1, lo0, lo1;
            {
                __nv_bfloat16 hx = __float2bfloat16(v.x), hy = __float2bfloat16(v.y);
                __nv_bfloat16 hz = __float2bfloat16(v.z), hw = __float2bfloat16(v.w);
                hi0 = (u32)__bfloat16_as_ushort(hx) | ((u32)__bfloat16_as_ushort(hy) << 16);
                hi1 = (u32)__bfloat16_as_ushort(hz) | ((u32)__bfloat16_as_ushort(hw) << 16);
                __nv_bfloat16 lx = __float2bfloat16(v.x - __bfloat162float(hx));
                __nv_bfloat16 ly = __float2bfloat16(v.y - __bfloat162float(hy));
                __nv_bfloat16 lz = __float2bfloat16(v.z - __bfloat162float(hz));
                __nv_bfloat16 lw = __float2bfloat16(v.w - __bfloat162float(hw));
                lo0 = (u32)__bfloat16_as_ushort(lx) | ((u32)__bfloat16_as_ushort(ly) << 16);
                lo1 = (u32)__bfloat16_as_ushort(lz) | ((u32)__bfloat16_as_ushort(lw) << 16);
            }
            u32 o = (u32)(p * 128) + (u32)((c0 * 2) ^ ((p & 7) << 4));
            *(uint2*)(base + A_HI_OFF + o) = make_uint2(hi0, hi1);
            *(uint2*)(base + A_LO_OFF + o) = make_uint2(lo0, lo1);
        }
        __syncthreads();

        // ---- mainloop: 4 chunks of 32 codes; 3 splits; top-2 via IMNMX keys ----
        u32 bK[4] = {0u,0u,0u,0u};
        u32 sK[4] = {0u,0u,0u,0u};
        const int m0  = 32 * wm;
        const int nb0 = 128 * wn;

        #pragma unroll
        for (int chunk = 0; chunk < 4; chunk++) {
            // acc[ntc][mt][4], init to biased half-norm pairs
            float acc[4][2][4];
            #pragma unroll
            for (int ntc = 0; ntc < 4; ntc++) {
                float2 h2 = *(const float2*)(hb + nb0 + chunk * 32 + ntc * 8 + 2 * q);
                #pragma unroll
                for (int mt = 0; mt < 2; mt++) {
                    acc[ntc][mt][0] = h2.x; acc[ntc][mt][1] = h2.y;
                    acc[ntc][mt][2] = h2.x; acc[ntc][mt][3] = h2.y;
                }
            }

            #pragma unroll
            for (int split = 0; split < 3; split++) {
                const u32 Ab = sb + ((split == 2) ? A_LO_OFF : A_HI_OFF);
                const u32 Bb = sb + ((split == 1) ? B_LO_OFF : B_HI_OFF);

                u32 a[2][4][4];
                #pragma unroll
                for (int mt = 0; mt < 2; mt++)
                    #pragma unroll
                    for (int ks = 0; ks < 4; ks++) {
                        u32 colb = (u32)(ks * 32 + a_kb * 16) ^ xorL;
                        u32 ad = Ab + (u32)((m0 + mt * 16 + a_row) * 128) + colb;
                        LDSM_X4(a[mt][ks][0], a[mt][ks][1], a[mt][ks][2], a[mt][ks][3], ad);
                    }

                #pragma unroll
                for (int np = 0; np < 2; np++) {
                    const int n0 = nb0 + chunk * 32 + np * 16;
                    #pragma unroll
                    for (int ks = 0; ks < 4; ks++) {
                        u32 b0, b1, b2, b3;
                        u32 colb = (u32)(ks * 32 + b_kb * 16) ^ xorL;
                        u32 bd = Bb + (u32)((n0 + b_row) * 128) + colb;
                        LDSM_X4(b0, b1, b2, b3, bd);
                        #pragma unroll
                        for (int mt = 0; mt < 2; mt++) {
                            MMA16816(acc[np*2+0][mt], a[mt][ks], b0, b1);
                            MMA16816(acc[np*2+1][mt], a[mt][ks], b2, b3);
                        }
                    }
                }
            }

            // chunk scoring: quantized keys + branchless top-2
            #pragma unroll
            for (int ntc = 0; ntc < 4; ntc++) {
                const int nt = chunk * 4 + ntc;
                const u32 jrL = (u32)(31 - (nt * 2 + 0));
                const u32 jrH = (u32)(31 - (nt * 2 + 1));
                #pragma unroll
                for (int mt = 0; mt < 2; mt++) {
                    u32 k0b = (__float_as_uint(acc[ntc][mt][0]) & ~31u) | jrL;
                    u32 k1b = (__float_as_uint(acc[ntc][mt][1]) & ~31u) | jrH;
                    u32 k2b = (__float_as_uint(acc[ntc][mt][2]) & ~31u) | jrL;
                    u32 k3b = (__float_as_uint(acc[ntc][mt][3]) & ~31u) | jrH;
                    int sA = mt * 2, sB = mt * 2 + 1;
                    sK[sA] = umax(sK[sA], umin(bK[sA], k0b)); bK[sA] = umax(bK[sA], k0b);
                    sK[sA] = umax(sK[sA], umin(bK[sA], k1b)); bK[sA] = umax(bK[sA], k1b);
                    sK[sB] = umax(sK[sB], umin(bK[sB], k2b)); bK[sB] = umax(bK[sB], k2b);
                    sK[sB] = umax(sK[sB], umin(bK[sB], k3b)); bK[sB] = umax(bK[sB], k3b);
                }
            }
        }

        // ---- decode + merge across 4 column lanes (xor 1,2) ----
        float vb[4], vs[4];
        int   kb[4], ks_[4];
        #pragma unroll
        for (int s = 0; s < 4; s++) {
            int j5 = 31 - (int)(bK[s] & 31u);
            kb[s] = nb0 + (j5 >> 1) * 8 + 2 * q + (j5 & 1);
            vb[s] = __uint_as_float(bK[s] & ~31u) - BIAS;
            j5 = 31 - (int)(sK[s] & 31u);
            ks_[s] = nb0 + (j5 >> 1) * 8 + 2 * q + (j5 & 1);
            vs[s] = __uint_as_float(sK[s] & ~31u) - BIAS;
        }
        #pragma unroll
        for (int m = 1; m < 4; m <<= 1) {
            #pragma unroll
            for (int s = 0; s < 4; s++) {
                float ovb = __shfl_xor_sync(0xFFFFFFFFu, vb[s], m);
                int   okb = __shfl_xor_sync(0xFFFFFFFFu, kb[s], m);
                float ovs = __shfl_xor_sync(0xFFFFFFFFu, vs[s], m);
                int   oks = __shfl_xor_sync(0xFFFFFFFFu, ks_[s], m);
                bool ow = (ovb > vb[s]) || (ovb == vb[s] && okb < kb[s]);
                float lv = ow ? vb[s] : ovb;  int lk = ow ? kb[s] : okb;
                float wv = ow ? ovs : vs[s];  int wk = ow ? oks : ks_[s];
                if (ow) { vb[s] = ovb; kb[s] = okb; }
                bool sw = (lv > wv) || (lv == wv && lk < wk);
                vs[s] = sw ? lv : wv;  ks_[s] = sw ? lk : wk;
            }
        }
        if (q == 0) {
            #pragma unroll
            for (int s = 0; s < 4; s++) {
                int p = 32 * wm + (lane >> 2) + s * 8;
                vb4[p * 4 + wn] = vb[s];  kb4[p * 4 + wn] = kb[s];
                vs4[p * 4 + wn] = vs[s];  ks4[p * 4 + wn] = ks_[s];
            }
        }
        __syncthreads();

        // ---- per-position merge (8 candidates) + fp64 exact refinement ----
        if (tid < POS) {
            const int p = tid;
            float gbv = -3.4e38f, gsv = -3.4e38f;
            int   gbi = 0x7fffffff, gsi = 0x7fffffff;
            #pragma unroll
            for (int c8 = 0; c8 < 8; c8++) {
                float v = (c8 < 4) ? vb4[p*4 + c8] : vs4[p*4 + (c8-4)];
                int   i = (c8 < 4) ? kb4[p*4 + c8] : ks4[p*4 + (c8-4)];
                if (v > gbv || (v == gbv && i < gbi)) {
                    gsv = gbv; gsi = gbi; gbv = v; gbi = i;
                } else if ((v > gsv || (v == gsv && i < gsi)) && i != gbi) {
                    gsv = v; gsi = i;
                }
            }
            if (gbv - gsv < MARGIN && gsi != gbi) {
                const float* c1 = cb + (size_t)gbi * DCH;
                const float* c2 = cb + (size_t)gsi * DCH;
                double db = 0.0, ds = 0.0;
                for (int c = 0; c < DCH; c++) {
                    double xv = (double)xs[p * XSTR + c];
                    double e1 = xv - (double)__ldg(c1 + c);
                    double e2 = xv - (double)__ldg(c2 + c);
                    db += e1 * e1;
                    ds += e2 * e2;
                }
                if (ds < db || (ds == db && gsi < gbi)) gbi = gsi;
            }
            idxs[p] = gbi;
        }
        __syncthreads();

        // ---- epilogue: codes = hi+lo reconstruction (rel err ~4e-6) ----
        for (int i4 = tid; i4 < (DCH*POS)/4; i4 += THREADS) {
            int c  = i4 >> 5;
            int p  = (i4 & 31) * 4;
            int hl = p >> 6, w = p & 63;
            float4 v;
            #pragma unroll
            for (int e = 0; e < 4; e++) {
                int k = idxs[p + e];
                u32 off = SW((u32)(k * 128 + c * 2));
                float hv = __bfloat162float(*(const __nv_bfloat16*)(base + B_HI_OFF + off));
                float lv = __bfloat162float(*(const __nv_bfloat16*)(base + B_LO_OFF + off));
                ((float*)&v)[e] = hv + lv;
            }
            *(float4*)(out + (((size_t)b * DCH + c) * HH + h0 + hl) * WW + w) = v;
        }
        if (write_idx && tid < POS) {
            int hl = tid >> 6, w = tid & 63;
            out[CODES_ELEMS + ((size_t)b * HH + h0 + hl) * WW + w] = (float)idxs[tid];
        }
    }
}

extern "C" void kernel_launch(void* const* d_in, const int* in_sizes, int n_in,
                              void* d_out, int out_size)
{
    const float* x  = (const float*)d_in[0];
    const float* cb = (const float*)d_in[1];
    float* out = (float*)d_out;

    int write_idx = ((size_t)out_size >= CODES_ELEMS + IDX_ELEMS) ? 1 : 0;

    int dev = 0;
    cudaGetDevice(&dev);
    int sms = 0;
    cudaDeviceGetAttribute(&sms, cudaDevAttrMultiProcessorCount, dev);
    if (sms <= 0) sms = 148;
    if (sms > NTILES) sms = NTILES;

    cudaFuncSetAttribute(vq_kernel, cudaFuncAttributeMaxDynamicSharedMemorySize,
                         (int)SMEM_BYTES);
    vq_kernel<<<sms, THREADS, SMEM_BYTES>>>(x, cb, out, write_idx);
}